// round 3
// baseline (speedup 1.0000x reference)
#include <cuda_runtime.h>

// Problem constants
#define BB 2
#define LL 2048
#define HH 1024
#define NHH 16
#define HDD 64
#define MM (BB*LL)   // 4096

// ---------------- scratch (static device globals; no allocation) -------------
__device__ float g_qT[BB*NHH*HDD*LL];   // [bh][d][l]  (Q pre-scaled by 1/8)
__device__ float g_kT[BB*NHH*HDD*LL];   // [bh][d][l]
__device__ float g_v [BB*NHH*LL*HDD];   // [bh][l][d]
__device__ float g_att[MM*HH];          // [b*L+l][h*64+d]
__device__ float g_bias[BB*NHH*LL];     // [bh][k]

// ---------------- gate / additive-bias kernel --------------------------------
// bias[b][h][k] = err[b,k]*sigmoid(x[b,k]@Wg[:,h]+bg[h]) + amask[b,k] + dbias[h]
__global__ void gate_bias_kernel(const float* __restrict__ x,
                                 const float* __restrict__ amask,
                                 const int*   __restrict__ err,
                                 const float* __restrict__ Wg,
                                 const float* __restrict__ bg,
                                 const float* __restrict__ dbias)
{
    __shared__ float red[128];
    int row = blockIdx.x;            // 0..4095 = b*L + l
    int tid = threadIdx.x;           // 128 threads: col = tid&15, seg = tid>>4
    int col = tid & 15;
    int seg = tid >> 4;
    const float* xr = x + row * HH;
    const int kbase = seg * 128;
    float acc = 0.f;
    #pragma unroll 8
    for (int kk = 0; kk < 128; kk++)
        acc += xr[kbase + kk] * Wg[(kbase + kk) * NHH + col];
    red[tid] = acc;
    __syncthreads();
    if (tid < 64) red[tid] += red[tid + 64];
    __syncthreads();
    if (tid < 32) red[tid] += red[tid + 32];
    __syncthreads();
    if (tid < 16) {
        float v = red[tid] + red[tid + 16] + bg[tid];
        float g = 1.f / (1.f + __expf(-v));
        int b = row >> 11;           // /L
        int l = row & (LL - 1);
        float bias = (float)err[row] * g + amask[row] + dbias[tid];
        g_bias[(b * NHH + tid) * LL + l] = bias;
    }
}

// ---------------- tiled SGEMM: Y = X[4096,1024] @ W[1024,1024] + bias --------
// MODE 0: Q  -> g_qT transposed per head, scaled by 0.125
// MODE 1: K  -> g_kT transposed per head
// MODE 2: V  -> g_v  head-major row layout
// MODE 3: plain -> out[m*1024+n]  (X taken from g_att)
#define GBM 128
#define GBN 128
#define GBK 16

template<int MODE>
__global__ void __launch_bounds__(256, 2)
gemm_kernel(const float* __restrict__ Xin, const float* __restrict__ W,
            const float* __restrict__ bias, float* __restrict__ out)
{
    __shared__ float As[GBK][GBM + 4];   // stride 132 (pad kills store conflicts)
    __shared__ float Bs[GBK][GBN];

    const float* X = (MODE == 3) ? (const float*)g_att : Xin;

    int tid = threadIdx.x;
    int tx = tid & 15;
    int ty = tid >> 4;
    int m0 = blockIdx.y * GBM;
    int n0 = blockIdx.x * GBN;

    float acc[8][8];
    #pragma unroll
    for (int i = 0; i < 8; i++)
        #pragma unroll
        for (int j = 0; j < 8; j++) acc[i][j] = 0.f;

    for (int k0 = 0; k0 < HH; k0 += GBK) {
        // A tile: 128 rows x 16 cols, stored transposed As[kk][m]
        #pragma unroll
        for (int it = 0; it < 2; it++) {
            int idx = tid + it * 256;          // 0..511
            int row = idx >> 2;
            int cq  = idx & 3;
            float4 v = *(const float4*)&X[(m0 + row) * HH + k0 + cq * 4];
            As[cq * 4 + 0][row] = v.x;
            As[cq * 4 + 1][row] = v.y;
            As[cq * 4 + 2][row] = v.z;
            As[cq * 4 + 3][row] = v.w;
        }
        // B tile: 16 rows x 128 cols
        #pragma unroll
        for (int it = 0; it < 2; it++) {
            int idx = tid + it * 256;          // 0..511
            int kk = idx >> 5;
            int cq = idx & 31;
            *(float4*)&Bs[kk][cq * 4] =
                *(const float4*)&W[(k0 + kk) * HH + n0 + cq * 4];
        }
        __syncthreads();

        #pragma unroll
        for (int kk = 0; kk < GBK; kk++) {
            float a[8], b[8];
            *(float4*)(a)     = *(const float4*)&As[kk][ty * 8];
            *(float4*)(a + 4) = *(const float4*)&As[kk][ty * 8 + 4];
            *(float4*)(b)     = *(const float4*)&Bs[kk][tx * 8];
            *(float4*)(b + 4) = *(const float4*)&Bs[kk][tx * 8 + 4];
            #pragma unroll
            for (int i = 0; i < 8; i++)
                #pragma unroll
                for (int j = 0; j < 8; j++)
                    acc[i][j] += a[i] * b[j];
        }
        __syncthreads();
    }

    // epilogue
    #pragma unroll
    for (int i = 0; i < 8; i++) {
        int m = m0 + ty * 8 + i;
        int b = m >> 11;
        int l = m & (LL - 1);
        #pragma unroll
        for (int j = 0; j < 8; j++) {
            int n = n0 + tx * 8 + j;
            float val = acc[i][j] + bias[n];
            int h = n >> 6;
            int d = n & 63;
            if (MODE == 0)
                g_qT[((b * NHH + h) * HDD + d) * LL + l] = val * 0.125f;
            else if (MODE == 1)
                g_kT[((b * NHH + h) * HDD + d) * LL + l] = val;
            else if (MODE == 2)
                g_v[((b * NHH + h) * LL + l) * HDD + d] = val;
            else
                out[m * HH + n] = val;
        }
    }
}

// ---------------- flash attention: 64x64 tiles, online softmax ---------------
__global__ void __launch_bounds__(256)
flash_kernel()
{
    __shared__ float Qt[64][64];     // Qt[d][r]  (Q already scaled by 1/8)
    __shared__ float KP[64 * 64];    // Kt[d][c] during S, then P[r][c] during PV
    __shared__ float Vs[64][64];     // V[c][d]

    int tid = threadIdx.x;
    int tx = tid & 15;
    int ty = tid >> 4;
    int bh = blockIdx.y;             // b*NH + h
    int q0 = blockIdx.x * 64;

    const float* qbase = g_qT + (size_t)bh * HDD * LL;
    const float* kbase = g_kT + (size_t)bh * HDD * LL;
    const float* vbase = g_v  + (size_t)bh * LL * HDD;
    const float* bbase = g_bias + (size_t)bh * LL;

    // load Q tile (64 d-rows x 64 l-cols), coalesced
    #pragma unroll
    for (int it = 0; it < 4; it++) {
        int idx = tid + it * 256;          // 0..1023
        int d  = idx >> 4;
        int cq = idx & 15;
        *(float4*)&Qt[d][cq * 4] = *(const float4*)&qbase[d * LL + q0 + cq * 4];
    }

    float acc[4][4];
    #pragma unroll
    for (int i = 0; i < 4; i++)
        #pragma unroll
        for (int j = 0; j < 4; j++) acc[i][j] = 0.f;
    float mrow[4] = {-1e30f, -1e30f, -1e30f, -1e30f};
    float lrow[4] = {0.f, 0.f, 0.f, 0.f};

    for (int k0 = 0; k0 < LL; k0 += 64) {
        __syncthreads();   // prev-iter PV reads of KP/Vs done; Qt stores visible (iter 0)
        // load K tile (transposed layout) and V tile
        #pragma unroll
        for (int it = 0; it < 4; it++) {
            int idx = tid + it * 256;
            int r  = idx >> 4;
            int cq = idx & 15;
            *(float4*)&KP[r * 64 + cq * 4] = *(const float4*)&kbase[r * LL + k0 + cq * 4];
            *(float4*)&Vs[r][cq * 4]       = *(const float4*)&vbase[(k0 + r) * HDD + cq * 4];
        }
        __syncthreads();

        // S = Q K^T  (per-thread 4x4)
        float s[4][4];
        #pragma unroll
        for (int i = 0; i < 4; i++)
            #pragma unroll
            for (int j = 0; j < 4; j++) s[i][j] = 0.f;

        #pragma unroll 8
        for (int d = 0; d < 64; d++) {
            float4 qv = *(const float4*)&Qt[d][ty * 4];
            float4 kv = *(const float4*)&KP[d * 64 + tx * 4];
            float qa[4] = {qv.x, qv.y, qv.z, qv.w};
            float ka[4] = {kv.x, kv.y, kv.z, kv.w};
            #pragma unroll
            for (int i = 0; i < 4; i++)
                #pragma unroll
                for (int j = 0; j < 4; j++)
                    s[i][j] += qa[i] * ka[j];
        }

        // additive bias per k column
        float bj[4];
        #pragma unroll
        for (int j = 0; j < 4; j++) bj[j] = bbase[k0 + tx * 4 + j];
        #pragma unroll
        for (int i = 0; i < 4; i++)
            #pragma unroll
            for (int j = 0; j < 4; j++)
                s[i][j] += bj[j];

        // online softmax update (row reduction across 16 tx lanes via shfl)
        #pragma unroll
        for (int i = 0; i < 4; i++) {
            float mx = fmaxf(fmaxf(s[i][0], s[i][1]), fmaxf(s[i][2], s[i][3]));
            #pragma unroll
            for (int off = 1; off < 16; off <<= 1)
                mx = fmaxf(mx, __shfl_xor_sync(0xffffffffu, mx, off));
            float mnew = fmaxf(mrow[i], mx);
            float corr = __expf(mrow[i] - mnew);
            mrow[i] = mnew;
            lrow[i] *= corr;
            #pragma unroll
            for (int j = 0; j < 4; j++) acc[i][j] *= corr;
            float rs = 0.f;
            #pragma unroll
            for (int j = 0; j < 4; j++) {
                float p = __expf(s[i][j] - mnew);
                s[i][j] = p;
                rs += p;
            }
            #pragma unroll
            for (int off = 1; off < 16; off <<= 1)
                rs += __shfl_xor_sync(0xffffffffu, rs, off);
            lrow[i] += rs;
        }

        __syncthreads();   // all Kt reads finished -> safe to overwrite KP with P
        #pragma unroll
        for (int i = 0; i < 4; i++) {
            float4 pv = make_float4(s[i][0], s[i][1], s[i][2], s[i][3]);
            *(float4*)&KP[(ty * 4 + i) * 64 + tx * 4] = pv;
        }
        __syncthreads();

        // O += P @ V
        #pragma unroll 8
        for (int c = 0; c < 64; c++) {
            float4 vv = *(const float4*)&Vs[c][tx * 4];
            float p0 = KP[(ty * 4 + 0) * 64 + c];
            float p1 = KP[(ty * 4 + 1) * 64 + c];
            float p2 = KP[(ty * 4 + 2) * 64 + c];
            float p3 = KP[(ty * 4 + 3) * 64 + c];
            acc[0][0] += p0 * vv.x; acc[0][1] += p0 * vv.y; acc[0][2] += p0 * vv.z; acc[0][3] += p0 * vv.w;
            acc[1][0] += p1 * vv.x; acc[1][1] += p1 * vv.y; acc[1][2] += p1 * vv.z; acc[1][3] += p1 * vv.w;
            acc[2][0] += p2 * vv.x; acc[2][1] += p2 * vv.y; acc[2][2] += p2 * vv.z; acc[2][3] += p2 * vv.w;
            acc[3][0] += p3 * vv.x; acc[3][1] += p3 * vv.y; acc[3][2] += p3 * vv.z; acc[3][3] += p3 * vv.w;
        }
    }

    // finalize + write to g_att [b*L+row][h*64+col]
    int b = bh >> 4;
    int h = bh & 15;
    #pragma unroll
    for (int i = 0; i < 4; i++) {
        int row = q0 + ty * 4 + i;
        float inv = 1.f / lrow[i];
        float4 o = make_float4(acc[i][0] * inv, acc[i][1] * inv,
                               acc[i][2] * inv, acc[i][3] * inv);
        *(float4*)&g_att[((size_t)(b * LL + row)) * HH + h * HDD + tx * 4] = o;
    }
}

// ---------------- launch ------------------------------------------------------
extern "C" void kernel_launch(void* const* d_in, const int* in_sizes, int n_in,
                              void* d_out, int out_size)
{
    const float* x     = (const float*)d_in[0];
    const float* amask = (const float*)d_in[1];
    const int*   err   = (const int*)  d_in[2];
    const float* Wq    = (const float*)d_in[3];
    const float* bq    = (const float*)d_in[4];
    const float* Wk    = (const float*)d_in[5];
    const float* bk    = (const float*)d_in[6];
    const float* Wv    = (const float*)d_in[7];
    const float* bv    = (const float*)d_in[8];
    const float* Wo    = (const float*)d_in[9];
    const float* bo    = (const float*)d_in[10];
    const float* dbias = (const float*)d_in[11];
    const float* Wg    = (const float*)d_in[12];
    const float* bg    = (const float*)d_in[13];
    float* out = (float*)d_out;

    dim3 ggrid(MM);                 // 4096 rows
    gate_bias_kernel<<<ggrid, 128>>>(x, amask, err, Wg, bg, dbias);

    dim3 grid(HH / GBN, MM / GBM);  // (8, 32)
    gemm_kernel<0><<<grid, 256>>>(x, Wq, bq, nullptr);
    gemm_kernel<1><<<grid, 256>>>(x, Wk, bk, nullptr);
    gemm_kernel<2><<<grid, 256>>>(x, Wv, bv, nullptr);

    dim3 fgrid(LL / 64, BB * NHH);  // (32, 32)
    flash_kernel<<<fgrid, 256>>>();

    gemm_kernel<3><<<grid, 256>>>(nullptr, Wo, bo, out);
}

// round 5
// speedup vs baseline: 1.4236x; 1.4236x over previous
#include <cuda_runtime.h>
#include <cuda_bf16.h>
#include <cstdint>

// Problem constants
#define BB 2
#define LL 2048
#define HH 1024
#define NHH 16
#define HDD 64
#define MM (BB*LL)   // 4096

// ---------------- scratch (static device globals; no allocation) -------------
__device__ float g_qT[BB*NHH*HDD*LL];   // [bh][d][l]  (Q pre-scaled by 1/8)
__device__ float g_kT[BB*NHH*HDD*LL];   // [bh][d][l]
__device__ float g_v [BB*NHH*LL*HDD];   // [bh][l][d]
__device__ float g_att[MM*HH];          // [b*L+l][h*64+d]
__device__ float g_bias[BB*NHH*LL];     // [bh][k]
__device__ float g_wT[4*HH*HH];         // transposed weights [n][k], 4 mats

// ================= helpers ====================================================
__device__ __forceinline__ uint32_t smem_u32(const void* p) {
    uint32_t a;
    asm("{ .reg .u64 t; cvta.to.shared.u64 t, %1; cvt.u32.u64 %0, t; }"
        : "=r"(a) : "l"(p));
    return a;
}
__device__ __forceinline__ void ldsm4(uint32_t* r, uint32_t addr) {
    asm volatile("ldmatrix.sync.aligned.m8n8.x4.shared.b16 {%0,%1,%2,%3}, [%4];"
        : "=r"(r[0]), "=r"(r[1]), "=r"(r[2]), "=r"(r[3]) : "r"(addr));
}
__device__ __forceinline__ void mma16816(float* c, const uint32_t* a,
                                         uint32_t b0, uint32_t b1) {
    asm volatile(
        "mma.sync.aligned.m16n8k16.row.col.f32.bf16.bf16.f32 "
        "{%0,%1,%2,%3}, {%4,%5,%6,%7}, {%8,%9}, {%0,%1,%2,%3};"
        : "+f"(c[0]), "+f"(c[1]), "+f"(c[2]), "+f"(c[3])
        : "r"(a[0]), "r"(a[1]), "r"(a[2]), "r"(a[3]), "r"(b0), "r"(b1));
}
__device__ __forceinline__ uint32_t pack2(float x, float y) {
    __nv_bfloat162 h = __floats2bfloat162_rn(x, y);
    return *reinterpret_cast<uint32_t*>(&h);
}

// ---------------- weight transpose (fp32) ------------------------------------
__global__ void wtrans_kernel(const float* __restrict__ W0, const float* __restrict__ W1,
                              const float* __restrict__ W2, const float* __restrict__ W3)
{
    __shared__ float t[32][33];
    int mat = blockIdx.z;
    const float* src = (mat == 0) ? W0 : (mat == 1) ? W1 : (mat == 2) ? W2 : W3;
    float* dst = g_wT + (size_t)mat * HH * HH;
    int x0 = blockIdx.x * 32, y0 = blockIdx.y * 32;
    int tx = threadIdx.x, ty = threadIdx.y;  // 32 x 8
    #pragma unroll
    for (int i = 0; i < 32; i += 8)
        t[ty + i][tx] = src[(size_t)(y0 + ty + i) * HH + x0 + tx];
    __syncthreads();
    #pragma unroll
    for (int i = 0; i < 32; i += 8)
        dst[(size_t)(x0 + ty + i) * HH + y0 + tx] = t[tx][ty + i];
}

// ---------------- gate / additive-bias kernel --------------------------------
__global__ void gate_bias_kernel(const float* __restrict__ x,
                                 const float* __restrict__ amask,
                                 const int*   __restrict__ err,
                                 const float* __restrict__ Wg,
                                 const float* __restrict__ bg,
                                 const float* __restrict__ dbias)
{
    __shared__ float red[128];
    int row = blockIdx.x;
    int tid = threadIdx.x;
    int col = tid & 15;
    int seg = tid >> 4;
    const float* xr = x + row * HH;
    const int kbase = seg * 128;
    float acc = 0.f;
    #pragma unroll 8
    for (int kk = 0; kk < 128; kk++)
        acc += xr[kbase + kk] * Wg[(kbase + kk) * NHH + col];
    red[tid] = acc;
    __syncthreads();
    if (tid < 64) red[tid] += red[tid + 64];
    __syncthreads();
    if (tid < 32) red[tid] += red[tid + 32];
    __syncthreads();
    if (tid < 16) {
        float v = red[tid] + red[tid + 16] + bg[tid];
        float g = 1.f / (1.f + __expf(-v));
        int b = row >> 11;
        int l = row & (LL - 1);
        float bias = (float)err[row] * g + amask[row] + dbias[tid];
        g_bias[(b * NHH + tid) * LL + l] = bias;
    }
}

// ---------------- bf16-split tensor-core GEMM --------------------------------
// D[m0:128, n0:128] = X[m0:128, :] @ Wt[n0:128, :]^T + bias  (fp32-accurate
// via 2-term bf16 split: ah*bh + ah*bl + al*bh)
// MODE 0: Q -> g_qT (scaled 0.125)  MODE 1: K -> g_kT
// MODE 2: V -> g_v                  MODE 3: out (A read from g_att)
#define TGM 128
#define TGN 128
#define TGK 32
#define ROWB 80                        // 40 bf16 per row (32 data + pad)
#define OFF_AHI 0
#define OFF_ALO 10240
#define OFF_BHI 20480
#define OFF_BLO 30720
#define TG_SMEM (128 * 132 * 4)        // epilogue staging dominates: 67584 B

template<int MODE>
__global__ void __launch_bounds__(256)
tgemm_kernel(const float* __restrict__ Xin, const float* __restrict__ bias,
             float* __restrict__ out, int wsel)
{
    extern __shared__ char dynsmem[];
    uint32_t sb = smem_u32(dynsmem);
    int tid = threadIdx.x;
    int lane = tid & 31;
    int wid = tid >> 5;

    const float* X  = (MODE == 3) ? (const float*)g_att : Xin;
    const float* Bt = g_wT + (size_t)wsel * HH * HH;
    int n0 = blockIdx.x * TGN;
    int m0 = blockIdx.y * TGM;

    // warp tile: 2 (m) x 4 (n) warps -> 64 x 32 each
    int m_base = (wid >> 2) * 64;
    int n_base = (wid & 3) * 32;

    // ldmatrix per-lane base addresses (80B row stride is phase-conflict-free)
    int t = lane >> 3;
    uint32_t a_addr = sb + OFF_AHI +
        (uint32_t)((m_base + (t & 1) * 8 + (lane & 7)) * ROWB + (t >> 1) * 16);
    uint32_t b_addr = sb + OFF_BHI +
        (uint32_t)((n_base + (t >> 1) * 8 + (lane & 7)) * ROWB + (t & 1) * 16);

    float acc[4][4][4];
    #pragma unroll
    for (int i = 0; i < 4; i++)
        #pragma unroll
        for (int j = 0; j < 4; j++)
            #pragma unroll
            for (int r = 0; r < 4; r++) acc[i][j][r] = 0.f;

    for (int k0 = 0; k0 < HH; k0 += TGK) {
        // ---- global -> split bf16 smem (A: 128x32, B: 128x32) ----
        #pragma unroll
        for (int i = 0; i < 4; i++) {
            int a = tid + 256 * i;                 // 0..1023
            int row = a >> 3, q = a & 7;
            float4 v = *(const float4*)&X[(size_t)(m0 + row) * HH + k0 + q * 4];
            float hx = __bfloat162float(__float2bfloat16(v.x));
            float hy = __bfloat162float(__float2bfloat16(v.y));
            float hz = __bfloat162float(__float2bfloat16(v.z));
            float hw = __bfloat162float(__float2bfloat16(v.w));
            uint32_t off = (uint32_t)(row * ROWB + q * 8);
            *(uint2*)(dynsmem + OFF_AHI + off) =
                make_uint2(pack2(hx, hy), pack2(hz, hw));
            *(uint2*)(dynsmem + OFF_ALO + off) =
                make_uint2(pack2(v.x - hx, v.y - hy), pack2(v.z - hz, v.w - hw));
        }
        #pragma unroll
        for (int i = 0; i < 4; i++) {
            int a = tid + 256 * i;
            int row = a >> 3, q = a & 7;
            float4 v = *(const float4*)&Bt[(size_t)(n0 + row) * HH + k0 + q * 4];
            float hx = __bfloat162float(__float2bfloat16(v.x));
            float hy = __bfloat162float(__float2bfloat16(v.y));
            float hz = __bfloat162float(__float2bfloat16(v.z));
            float hw = __bfloat162float(__float2bfloat16(v.w));
            uint32_t off = (uint32_t)(row * ROWB + q * 8);
            *(uint2*)(dynsmem + OFF_BHI + off) =
                make_uint2(pack2(hx, hy), pack2(hz, hw));
            *(uint2*)(dynsmem + OFF_BLO + off) =
                make_uint2(pack2(v.x - hx, v.y - hy), pack2(v.z - hz, v.w - hw));
        }
        __syncthreads();

        // ---- 2 x k16 MMA steps ----
        #pragma unroll
        for (int kk = 0; kk < 2; kk++) {
            uint32_t ah[4][4], al[4][4], bh[2][4], bl[2][4];
            #pragma unroll
            for (int mt = 0; mt < 4; mt++) {
                uint32_t ad = a_addr + mt * (16 * ROWB) + kk * 32;
                ldsm4(ah[mt], ad);
                ldsm4(al[mt], ad + (OFF_ALO - OFF_AHI));
            }
            #pragma unroll
            for (int np = 0; np < 2; np++) {
                uint32_t bd = b_addr + np * (16 * ROWB) + kk * 32;
                ldsm4(bh[np], bd);
                ldsm4(bl[np], bd + (OFF_BLO - OFF_BHI));
            }
            #pragma unroll
            for (int mt = 0; mt < 4; mt++)
                #pragma unroll
                for (int nt = 0; nt < 4; nt++) {
                    int np = nt >> 1, e = (nt & 1) * 2;
                    mma16816(acc[mt][nt], ah[mt], bh[np][e], bh[np][e + 1]);
                    mma16816(acc[mt][nt], ah[mt], bl[np][e], bl[np][e + 1]);
                    mma16816(acc[mt][nt], al[mt], bh[np][e], bh[np][e + 1]);
                }
        }
        __syncthreads();
    }

    // ---- epilogue: frags -> smem staging (bias, mode scale) ----
    float* sD = (float*)dynsmem;
    int g = lane >> 2, cb = (lane & 3) * 2;
    #pragma unroll
    for (int mt = 0; mt < 4; mt++)
        #pragma unroll
        for (int nt = 0; nt < 4; nt++)
            #pragma unroll
            for (int r = 0; r < 4; r++) {
                int row = m_base + mt * 16 + (r >> 1) * 8 + g;
                int col = n_base + nt * 8 + cb + (r & 1);
                float v = acc[mt][nt][r] + bias[n0 + col];
                if (MODE == 0) v *= 0.125f;
                sD[row * 132 + col] = v;
            }
    __syncthreads();

    // ---- smem -> global, coalesced per mode ----
    int b  = m0 >> 11;
    int l0 = m0 & (LL - 1);
    if (MODE == 0 || MODE == 1) {
        float* dst = (MODE == 0) ? g_qT : g_kT;
        for (int idx = tid; idx < TGM * TGN; idx += 256) {
            int mi = idx & 127, nl = idx >> 7;       // lanes span mi -> coalesced l
            int n = n0 + nl, h = n >> 6, d = n & 63;
            dst[((size_t)(b * NHH + h) * HDD + d) * LL + l0 + mi] = sD[mi * 132 + nl];
        }
    } else if (MODE == 2) {
        for (int idx = tid; idx < TGM * TGN; idx += 256) {
            int nl = idx & 127, mi = idx >> 7;       // lanes span nl -> coalesced d
            int n = n0 + nl, h = n >> 6, d = n & 63;
            g_v[((size_t)(b * NHH + h) * LL + l0 + mi) * HDD + d] = sD[mi * 132 + nl];
        }
    } else {
        for (int idx = tid; idx < TGM * TGN; idx += 256) {
            int nl = idx & 127, mi = idx >> 7;
            out[(size_t)(m0 + mi) * HH + n0 + nl] = sD[mi * 132 + nl];
        }
    }
}

// ---------------- flash attention: 64x64 tiles, online softmax ---------------
__global__ void __launch_bounds__(256)
flash_kernel()
{
    __shared__ float Qt[64][64];
    __shared__ float KP[64 * 64];
    __shared__ float Vs[64][64];

    int tid = threadIdx.x;
    int tx = tid & 15;
    int ty = tid >> 4;
    int bh = blockIdx.y;
    int q0 = blockIdx.x * 64;

    const float* qbase = g_qT + (size_t)bh * HDD * LL;
    const float* kbase = g_kT + (size_t)bh * HDD * LL;
    const float* vbase = g_v  + (size_t)bh * LL * HDD;
    const float* bbase = g_bias + (size_t)bh * LL;

    #pragma unroll
    for (int it = 0; it < 4; it++) {
        int idx = tid + it * 256;
        int d  = idx >> 4;
        int cq = idx & 15;
        *(float4*)&Qt[d][cq * 4] = *(const float4*)&qbase[d * LL + q0 + cq * 4];
    }

    float acc[4][4];
    #pragma unroll
    for (int i = 0; i < 4; i++)
        #pragma unroll
        for (int j = 0; j < 4; j++) acc[i][j] = 0.f;
    float mrow[4] = {-1e30f, -1e30f, -1e30f, -1e30f};
    float lrow[4] = {0.f, 0.f, 0.f, 0.f};

    for (int k0 = 0; k0 < LL; k0 += 64) {
        __syncthreads();
        #pragma unroll
        for (int it = 0; it < 4; it++) {
            int idx = tid + it * 256;
            int r  = idx >> 4;
            int cq = idx & 15;
            *(float4*)&KP[r * 64 + cq * 4] = *(const float4*)&kbase[r * LL + k0 + cq * 4];
            *(float4*)&Vs[r][cq * 4]       = *(const float4*)&vbase[(k0 + r) * HDD + cq * 4];
        }
        __syncthreads();

        float s[4][4];
        #pragma unroll
        for (int i = 0; i < 4; i++)
            #pragma unroll
            for (int j = 0; j < 4; j++) s[i][j] = 0.f;

        #pragma unroll 8
        for (int d = 0; d < 64; d++) {
            float4 qv = *(const float4*)&Qt[d][ty * 4];
            float4 kv = *(const float4*)&KP[d * 64 + tx * 4];
            float qa[4] = {qv.x, qv.y, qv.z, qv.w};
            float ka[4] = {kv.x, kv.y, kv.z, kv.w};
            #pragma unroll
            for (int i = 0; i < 4; i++)
                #pragma unroll
                for (int j = 0; j < 4; j++)
                    s[i][j] += qa[i] * ka[j];
        }

        float bj[4];
        #pragma unroll
        for (int j = 0; j < 4; j++) bj[j] = bbase[k0 + tx * 4 + j];
        #pragma unroll
        for (int i = 0; i < 4; i++)
            #pragma unroll
            for (int j = 0; j < 4; j++)
                s[i][j] += bj[j];

        #pragma unroll
        for (int i = 0; i < 4; i++) {
            float mx = fmaxf(fmaxf(s[i][0], s[i][1]), fmaxf(s[i][2], s[i][3]));
            #pragma unroll
            for (int off = 1; off < 16; off <<= 1)
                mx = fmaxf(mx, __shfl_xor_sync(0xffffffffu, mx, off));
            float mnew = fmaxf(mrow[i], mx);
            float corr = __expf(mrow[i] - mnew);
            mrow[i] = mnew;
            lrow[i] *= corr;
            #pragma unroll
            for (int j = 0; j < 4; j++) acc[i][j] *= corr;
            float rs = 0.f;
            #pragma unroll
            for (int j = 0; j < 4; j++) {
                float p = __expf(s[i][j] - mnew);
                s[i][j] = p;
                rs += p;
            }
            #pragma unroll
            for (int off = 1; off < 16; off <<= 1)
                rs += __shfl_xor_sync(0xffffffffu, rs, off);
            lrow[i] += rs;
        }

        __syncthreads();
        #pragma unroll
        for (int i = 0; i < 4; i++) {
            float4 pv = make_float4(s[i][0], s[i][1], s[i][2], s[i][3]);
            *(float4*)&KP[(ty * 4 + i) * 64 + tx * 4] = pv;
        }
        __syncthreads();

        #pragma unroll 8
        for (int c = 0; c < 64; c++) {
            float4 vv = *(const float4*)&Vs[c][tx * 4];
            float p0 = KP[(ty * 4 + 0) * 64 + c];
            float p1 = KP[(ty * 4 + 1) * 64 + c];
            float p2 = KP[(ty * 4 + 2) * 64 + c];
            float p3 = KP[(ty * 4 + 3) * 64 + c];
            acc[0][0] += p0 * vv.x; acc[0][1] += p0 * vv.y; acc[0][2] += p0 * vv.z; acc[0][3] += p0 * vv.w;
            acc[1][0] += p1 * vv.x; acc[1][1] += p1 * vv.y; acc[1][2] += p1 * vv.z; acc[1][3] += p1 * vv.w;
            acc[2][0] += p2 * vv.x; acc[2][1] += p2 * vv.y; acc[2][2] += p2 * vv.z; acc[2][3] += p2 * vv.w;
            acc[3][0] += p3 * vv.x; acc[3][1] += p3 * vv.y; acc[3][2] += p3 * vv.z; acc[3][3] += p3 * vv.w;
        }
    }

    int b = bh >> 4;
    int h = bh & 15;
    #pragma unroll
    for (int i = 0; i < 4; i++) {
        int row = q0 + ty * 4 + i;
        float inv = 1.f / lrow[i];
        float4 o = make_float4(acc[i][0] * inv, acc[i][1] * inv,
                               acc[i][2] * inv, acc[i][3] * inv);
        *(float4*)&g_att[((size_t)(b * LL + row)) * HH + h * HDD + tx * 4] = o;
    }
}

// ---------------- launch ------------------------------------------------------
extern "C" void kernel_launch(void* const* d_in, const int* in_sizes, int n_in,
                              void* d_out, int out_size)
{
    const float* x     = (const float*)d_in[0];
    const float* amask = (const float*)d_in[1];
    const int*   err   = (const int*)  d_in[2];
    const float* Wq    = (const float*)d_in[3];
    const float* bq    = (const float*)d_in[4];
    const float* Wk    = (const float*)d_in[5];
    const float* bk    = (const float*)d_in[6];
    const float* Wv    = (const float*)d_in[7];
    const float* bv    = (const float*)d_in[8];
    const float* Wo    = (const float*)d_in[9];
    const float* bo    = (const float*)d_in[10];
    const float* dbias = (const float*)d_in[11];
    const float* Wg    = (const float*)d_in[12];
    const float* bg    = (const float*)d_in[13];
    float* out = (float*)d_out;

    cudaFuncSetAttribute(tgemm_kernel<0>, cudaFuncAttributeMaxDynamicSharedMemorySize, TG_SMEM);
    cudaFuncSetAttribute(tgemm_kernel<1>, cudaFuncAttributeMaxDynamicSharedMemorySize, TG_SMEM);
    cudaFuncSetAttribute(tgemm_kernel<2>, cudaFuncAttributeMaxDynamicSharedMemorySize, TG_SMEM);
    cudaFuncSetAttribute(tgemm_kernel<3>, cudaFuncAttributeMaxDynamicSharedMemorySize, TG_SMEM);

    dim3 tb(32, 8);
    dim3 tg(HH / 32, HH / 32, 4);
    wtrans_kernel<<<tg, tb>>>(Wq, Wk, Wv, Wo);

    gate_bias_kernel<<<MM, 128>>>(x, amask, err, Wg, bg, dbias);

    dim3 grid(HH / TGN, MM / TGM);   // (8, 32) = 256 CTAs
    tgemm_kernel<0><<<grid, 256, TG_SMEM>>>(x, bq, nullptr, 0);
    tgemm_kernel<1><<<grid, 256, TG_SMEM>>>(x, bk, nullptr, 1);
    tgemm_kernel<2><<<grid, 256, TG_SMEM>>>(x, bv, nullptr, 2);

    dim3 fgrid(LL / 64, BB * NHH);
    flash_kernel<<<fgrid, 256>>>();

    tgemm_kernel<3><<<grid, 256, TG_SMEM>>>(nullptr, bo, out, 3);
}

// round 6
// speedup vs baseline: 2.6080x; 1.8319x over previous
#include <cuda_runtime.h>
#include <cuda_bf16.h>
#include <cstdint>

// Problem constants
#define BB 2
#define LL 2048
#define HH 1024
#define NHH 16
#define HDD 64
#define MM (BB*LL)   // 4096
#define BH (BB*NHH)  // 32

// ---------------- scratch (static device globals; no allocation) -------------
// Q/K/V stored as bf16 hi/lo pairs packed 2-per-uint32.
// Q,K: [bh][l][d]  (32 uint32 per row);  V: [bh][d][l]
__device__ uint32_t g_qh[BH*LL*32], g_ql[BH*LL*32];
__device__ uint32_t g_kh[BH*LL*32], g_kl[BH*LL*32];
__device__ uint32_t g_vh[BH*HDD*(LL/2)], g_vl[BH*HDD*(LL/2)];
__device__ float g_att[MM*HH];          // [b*L+l][h*64+d]
__device__ float g_bias[BH*LL];         // [bh][k]
__device__ float g_wT[4*HH*HH];         // transposed weights [n][k], 4 mats

// ================= helpers ====================================================
__device__ __forceinline__ uint32_t smem_u32(const void* p) {
    uint32_t a;
    asm("{ .reg .u64 t; cvta.to.shared.u64 t, %1; cvt.u32.u64 %0, t; }"
        : "=r"(a) : "l"(p));
    return a;
}
__device__ __forceinline__ void ldsm4(uint32_t* r, uint32_t addr) {
    asm volatile("ldmatrix.sync.aligned.m8n8.x4.shared.b16 {%0,%1,%2,%3}, [%4];"
        : "=r"(r[0]), "=r"(r[1]), "=r"(r[2]), "=r"(r[3]) : "r"(addr));
}
__device__ __forceinline__ void mma16816(float* c, const uint32_t* a,
                                         uint32_t b0, uint32_t b1) {
    asm volatile(
        "mma.sync.aligned.m16n8k16.row.col.f32.bf16.bf16.f32 "
        "{%0,%1,%2,%3}, {%4,%5,%6,%7}, {%8,%9}, {%0,%1,%2,%3};"
        : "+f"(c[0]), "+f"(c[1]), "+f"(c[2]), "+f"(c[3])
        : "r"(a[0]), "r"(a[1]), "r"(a[2]), "r"(a[3]), "r"(b0), "r"(b1));
}
__device__ __forceinline__ uint32_t pack2(float x, float y) {
    __nv_bfloat162 h = __floats2bfloat162_rn(x, y);
    return *reinterpret_cast<uint32_t*>(&h);
}
__device__ __forceinline__ float bhi(float x) {
    return __bfloat162float(__float2bfloat16(x));
}

// ---------------- weight transpose (fp32) ------------------------------------
__global__ void wtrans_kernel(const float* __restrict__ W0, const float* __restrict__ W1,
                              const float* __restrict__ W2, const float* __restrict__ W3)
{
    __shared__ float t[32][33];
    int mat = blockIdx.z;
    const float* src = (mat == 0) ? W0 : (mat == 1) ? W1 : (mat == 2) ? W2 : W3;
    float* dst = g_wT + (size_t)mat * HH * HH;
    int x0 = blockIdx.x * 32, y0 = blockIdx.y * 32;
    int tx = threadIdx.x, ty = threadIdx.y;  // 32 x 8
    #pragma unroll
    for (int i = 0; i < 32; i += 8)
        t[ty + i][tx] = src[(size_t)(y0 + ty + i) * HH + x0 + tx];
    __syncthreads();
    #pragma unroll
    for (int i = 0; i < 32; i += 8)
        dst[(size_t)(x0 + ty + i) * HH + y0 + tx] = t[tx][ty + i];
}

// ---------------- gate / additive-bias kernel --------------------------------
__global__ void gate_bias_kernel(const float* __restrict__ x,
                                 const float* __restrict__ amask,
                                 const int*   __restrict__ err,
                                 const float* __restrict__ Wg,
                                 const float* __restrict__ bg,
                                 const float* __restrict__ dbias)
{
    __shared__ float red[128];
    int row = blockIdx.x;
    int tid = threadIdx.x;
    int col = tid & 15;
    int seg = tid >> 4;
    const float* xr = x + row * HH;
    const int kbase = seg * 128;
    float acc = 0.f;
    #pragma unroll 8
    for (int kk = 0; kk < 128; kk++)
        acc += xr[kbase + kk] * Wg[(kbase + kk) * NHH + col];
    red[tid] = acc;
    __syncthreads();
    if (tid < 64) red[tid] += red[tid + 64];
    __syncthreads();
    if (tid < 32) red[tid] += red[tid + 32];
    __syncthreads();
    if (tid < 16) {
        float v = red[tid] + red[tid + 16] + bg[tid];
        float g = 1.f / (1.f + __expf(-v));
        int b = row >> 11;
        int l = row & (LL - 1);
        float bias = (float)err[row] * g + amask[row] + dbias[tid];
        g_bias[(b * NHH + tid) * LL + l] = bias;
    }
}

// ---------------- bf16-split tensor-core GEMM --------------------------------
// MODE 0: Q -> g_qh/g_ql (scaled 0.125)   MODE 1: K -> g_kh/g_kl
// MODE 2: V -> g_vh/g_vl                  MODE 3: out (A read from g_att)
#define TGM 128
#define TGN 128
#define TGK 32
#define ROWB 80
#define OFF_AHI 0
#define OFF_ALO 10240
#define OFF_BHI 20480
#define OFF_BLO 30720
#define TG_SMEM (128 * 132 * 4)        // epilogue staging dominates: 67584 B

template<int MODE>
__global__ void __launch_bounds__(256)
tgemm_kernel(const float* __restrict__ Xin, const float* __restrict__ bias,
             float* __restrict__ out, int wsel)
{
    extern __shared__ char dynsmem[];
    uint32_t sb = smem_u32(dynsmem);
    int tid = threadIdx.x;
    int lane = tid & 31;
    int wid = tid >> 5;

    const float* X  = (MODE == 3) ? (const float*)g_att : Xin;
    const float* Bt = g_wT + (size_t)wsel * HH * HH;
    int n0 = blockIdx.x * TGN;
    int m0 = blockIdx.y * TGM;

    int m_base = (wid >> 2) * 64;
    int n_base = (wid & 3) * 32;

    int t = lane >> 3;
    uint32_t a_addr = sb + OFF_AHI +
        (uint32_t)((m_base + (t & 1) * 8 + (lane & 7)) * ROWB + (t >> 1) * 16);
    uint32_t b_addr = sb + OFF_BHI +
        (uint32_t)((n_base + (t >> 1) * 8 + (lane & 7)) * ROWB + (t & 1) * 16);

    float acc[4][4][4];
    #pragma unroll
    for (int i = 0; i < 4; i++)
        #pragma unroll
        for (int j = 0; j < 4; j++)
            #pragma unroll
            for (int r = 0; r < 4; r++) acc[i][j][r] = 0.f;

    for (int k0 = 0; k0 < HH; k0 += TGK) {
        #pragma unroll
        for (int i = 0; i < 4; i++) {
            int a = tid + 256 * i;
            int row = a >> 3, q = a & 7;
            float4 v = *(const float4*)&X[(size_t)(m0 + row) * HH + k0 + q * 4];
            float hx = bhi(v.x), hy = bhi(v.y), hz = bhi(v.z), hw = bhi(v.w);
            uint32_t off = (uint32_t)(row * ROWB + q * 8);
            *(uint2*)(dynsmem + OFF_AHI + off) =
                make_uint2(pack2(hx, hy), pack2(hz, hw));
            *(uint2*)(dynsmem + OFF_ALO + off) =
                make_uint2(pack2(v.x - hx, v.y - hy), pack2(v.z - hz, v.w - hw));
        }
        #pragma unroll
        for (int i = 0; i < 4; i++) {
            int a = tid + 256 * i;
            int row = a >> 3, q = a & 7;
            float4 v = *(const float4*)&Bt[(size_t)(n0 + row) * HH + k0 + q * 4];
            float hx = bhi(v.x), hy = bhi(v.y), hz = bhi(v.z), hw = bhi(v.w);
            uint32_t off = (uint32_t)(row * ROWB + q * 8);
            *(uint2*)(dynsmem + OFF_BHI + off) =
                make_uint2(pack2(hx, hy), pack2(hz, hw));
            *(uint2*)(dynsmem + OFF_BLO + off) =
                make_uint2(pack2(v.x - hx, v.y - hy), pack2(v.z - hz, v.w - hw));
        }
        __syncthreads();

        #pragma unroll
        for (int kk = 0; kk < 2; kk++) {
            uint32_t ah[4][4], al[4][4], bh4[2][4], bl4[2][4];
            #pragma unroll
            for (int mt = 0; mt < 4; mt++) {
                uint32_t ad = a_addr + mt * (16 * ROWB) + kk * 32;
                ldsm4(ah[mt], ad);
                ldsm4(al[mt], ad + (OFF_ALO - OFF_AHI));
            }
            #pragma unroll
            for (int np = 0; np < 2; np++) {
                uint32_t bd = b_addr + np * (16 * ROWB) + kk * 32;
                ldsm4(bh4[np], bd);
                ldsm4(bl4[np], bd + (OFF_BLO - OFF_BHI));
            }
            #pragma unroll
            for (int mt = 0; mt < 4; mt++)
                #pragma unroll
                for (int nt = 0; nt < 4; nt++) {
                    int np = nt >> 1, e = (nt & 1) * 2;
                    mma16816(acc[mt][nt], ah[mt], bh4[np][e], bh4[np][e + 1]);
                    mma16816(acc[mt][nt], ah[mt], bl4[np][e], bl4[np][e + 1]);
                    mma16816(acc[mt][nt], al[mt], bh4[np][e], bh4[np][e + 1]);
                }
        }
        __syncthreads();
    }

    // ---- epilogue: frags -> smem staging (bias, mode scale) ----
    float* sD = (float*)dynsmem;
    int g = lane >> 2, cb = (lane & 3) * 2;
    #pragma unroll
    for (int mt = 0; mt < 4; mt++)
        #pragma unroll
        for (int nt = 0; nt < 4; nt++)
            #pragma unroll
            for (int r = 0; r < 4; r++) {
                int row = m_base + mt * 16 + (r >> 1) * 8 + g;
                int col = n_base + nt * 8 + cb + (r & 1);
                float v = acc[mt][nt][r] + bias[n0 + col];
                if (MODE == 0) v *= 0.125f;
                sD[row * 132 + col] = v;
            }
    __syncthreads();

    // ---- smem -> global: bf16 hi/lo packed pairs per mode ----
    int b  = m0 >> 11;
    int l0 = m0 & (LL - 1);
    if (MODE == 0 || MODE == 1) {
        uint32_t* dh = (MODE == 0) ? g_qh : g_kh;
        uint32_t* dl = (MODE == 0) ? g_ql : g_kl;
        for (int idx = tid; idx < 8192; idx += 256) {
            int dp = idx & 31;           // d-pair (coalesced across lanes)
            int hseg = (idx >> 5) & 1;
            int mi = idx >> 6;
            int nl = hseg * 64 + dp * 2;
            float v0 = sD[mi * 132 + nl], v1 = sD[mi * 132 + nl + 1];
            float h0 = bhi(v0), h1 = bhi(v1);
            int n = n0 + nl, h = n >> 6;
            size_t o = (size_t)((b * NHH + h) * LL + l0 + mi) * 32 + dp;
            dh[o] = pack2(h0, h1);
            dl[o] = pack2(v0 - h0, v1 - h1);
        }
    } else if (MODE == 2) {
        for (int idx = tid; idx < 8192; idx += 256) {
            int lp = idx & 63;           // l-pair (coalesced across lanes)
            int nl = idx >> 6;
            float v0 = sD[(2 * lp) * 132 + nl], v1 = sD[(2 * lp + 1) * 132 + nl];
            float h0 = bhi(v0), h1 = bhi(v1);
            int n = n0 + nl, h = n >> 6, d = n & 63;
            size_t o = (size_t)((b * NHH + h) * HDD + d) * (LL / 2) + l0 / 2 + lp;
            g_vh[o] = pack2(h0, h1);
            g_vl[o] = pack2(v0 - h0, v1 - h1);
        }
    } else {
        for (int idx = tid; idx < TGM * TGN; idx += 256) {
            int nl = idx & 127, mi = idx >> 7;
            out[(size_t)(m0 + mi) * HH + n0 + nl] = sD[mi * 132 + nl];
        }
    }
}

// ---------------- tensor-core flash attention ---------------------------------
// CTA: 128 threads / 4 warps; 64 q-rows x 64 k-cols tiles; HD=64.
#define FROWB 144                 // smem row stride (64 bf16 data + pad), 9x16B
#define FQH 0
#define FQL 9216
#define FKH 18432
#define FKL 27648
#define FVH 36864
#define FVL 46080
#define FBIAS 55296
#define FL_SMEM (55296 + 256)

__global__ void __launch_bounds__(128)
flash_kernel()
{
    extern __shared__ char fsm[];
    uint32_t sb = smem_u32(fsm);
    int tid = threadIdx.x;
    int lane = tid & 31;
    int wid = tid >> 5;
    int bh = blockIdx.y;
    int q0 = blockIdx.x * 64;

    const char* qh = (const char*)g_qh;
    const char* ql = (const char*)g_ql;
    const char* kh = (const char*)g_kh;
    const char* kl = (const char*)g_kl;
    const char* vh = (const char*)g_vh;
    const char* vl = (const char*)g_vl;

    // load Q tile hi/lo: rows q0..q0+63, 128B each
    #pragma unroll
    for (int i = 0; i < 4; i++) {
        int c = tid + i * 128;           // 0..511
        int r = c >> 3, q8 = c & 7;
        size_t go = (size_t)(bh * LL + q0 + r) * 128 + q8 * 16;
        *(uint4*)(fsm + FQH + r * FROWB + q8 * 16) = *(const uint4*)(qh + go);
        *(uint4*)(fsm + FQL + r * FROWB + q8 * 16) = *(const uint4*)(ql + go);
    }

    // ldmatrix base addresses
    int t8 = lane >> 3;
    uint32_t qa = sb + FQH +
        (uint32_t)((wid * 16 + (t8 & 1) * 8 + (lane & 7)) * FROWB + (t8 >> 1) * 16);
    uint32_t kb = sb + FKH +
        (uint32_t)(((t8 >> 1) * 8 + (lane & 7)) * FROWB + (t8 & 1) * 16);
    uint32_t vb = sb + FVH +
        (uint32_t)(((t8 >> 1) * 8 + (lane & 7)) * FROWB + (t8 & 1) * 16);

    float o[8][4];
    #pragma unroll
    for (int i = 0; i < 8; i++)
        #pragma unroll
        for (int r = 0; r < 4; r++) o[i][r] = 0.f;
    float m0r = -1e30f, m1r = -1e30f, ls0 = 0.f, ls1 = 0.f;

    for (int k0 = 0; k0 < LL; k0 += 64) {
        __syncthreads();
        #pragma unroll
        for (int i = 0; i < 4; i++) {
            int c = tid + i * 128;
            int r = c >> 3, q8 = c & 7;
            size_t gk = (size_t)(bh * LL + k0 + r) * 128 + q8 * 16;
            size_t gv = (size_t)(bh * HDD + r) * (LL * 2) + k0 * 2 + q8 * 16;
            *(uint4*)(fsm + FKH + r * FROWB + q8 * 16) = *(const uint4*)(kh + gk);
            *(uint4*)(fsm + FKL + r * FROWB + q8 * 16) = *(const uint4*)(kl + gk);
            *(uint4*)(fsm + FVH + r * FROWB + q8 * 16) = *(const uint4*)(vh + gv);
            *(uint4*)(fsm + FVL + r * FROWB + q8 * 16) = *(const uint4*)(vl + gv);
        }
        if (tid < 64)
            ((float*)(fsm + FBIAS))[tid] = g_bias[bh * LL + k0 + tid];
        __syncthreads();

        // ---- S = Q K^T (3-term bf16 split) ----
        float s[8][4];
        #pragma unroll
        for (int i = 0; i < 8; i++)
            #pragma unroll
            for (int r = 0; r < 4; r++) s[i][r] = 0.f;

        #pragma unroll
        for (int kk = 0; kk < 4; kk++) {
            uint32_t ah[4], al[4];
            ldsm4(ah, qa + kk * 32);
            ldsm4(al, qa + kk * 32 + (FQL - FQH));
            #pragma unroll
            for (int nb = 0; nb < 4; nb++) {
                uint32_t bh4[4], bl4[4];
                uint32_t ba = kb + nb * (16 * FROWB) + kk * 32;
                ldsm4(bh4, ba);
                ldsm4(bl4, ba + (FKL - FKH));
                mma16816(s[2 * nb],     ah, bh4[0], bh4[1]);
                mma16816(s[2 * nb],     ah, bl4[0], bl4[1]);
                mma16816(s[2 * nb],     al, bh4[0], bh4[1]);
                mma16816(s[2 * nb + 1], ah, bh4[2], bh4[3]);
                mma16816(s[2 * nb + 1], ah, bl4[2], bl4[3]);
                mma16816(s[2 * nb + 1], al, bh4[2], bh4[3]);
            }
        }

        // ---- bias + online softmax on frag layout ----
        const float* sbias = (const float*)(fsm + FBIAS);
        int cb = (lane & 3) * 2;
        float mx0 = -1e30f, mx1 = -1e30f;
        #pragma unroll
        for (int nf = 0; nf < 8; nf++) {
            float b0 = sbias[nf * 8 + cb], b1 = sbias[nf * 8 + cb + 1];
            s[nf][0] += b0; s[nf][1] += b1;
            s[nf][2] += b0; s[nf][3] += b1;
            mx0 = fmaxf(mx0, fmaxf(s[nf][0], s[nf][1]));
            mx1 = fmaxf(mx1, fmaxf(s[nf][2], s[nf][3]));
        }
        mx0 = fmaxf(mx0, __shfl_xor_sync(0xffffffffu, mx0, 1));
        mx0 = fmaxf(mx0, __shfl_xor_sync(0xffffffffu, mx0, 2));
        mx1 = fmaxf(mx1, __shfl_xor_sync(0xffffffffu, mx1, 1));
        mx1 = fmaxf(mx1, __shfl_xor_sync(0xffffffffu, mx1, 2));
        float mn0 = fmaxf(m0r, mx0), mn1 = fmaxf(m1r, mx1);
        float c0 = __expf(m0r - mn0), c1 = __expf(m1r - mn1);
        m0r = mn0; m1r = mn1;
        ls0 *= c0; ls1 *= c1;
        #pragma unroll
        for (int nf = 0; nf < 8; nf++) {
            o[nf][0] *= c0; o[nf][1] *= c0;
            o[nf][2] *= c1; o[nf][3] *= c1;
        }
        float rs0 = 0.f, rs1 = 0.f;
        #pragma unroll
        for (int nf = 0; nf < 8; nf++) {
            s[nf][0] = __expf(s[nf][0] - mn0);
            s[nf][1] = __expf(s[nf][1] - mn0);
            s[nf][2] = __expf(s[nf][2] - mn1);
            s[nf][3] = __expf(s[nf][3] - mn1);
            rs0 += s[nf][0] + s[nf][1];
            rs1 += s[nf][2] + s[nf][3];
        }
        rs0 += __shfl_xor_sync(0xffffffffu, rs0, 1);
        rs0 += __shfl_xor_sync(0xffffffffu, rs0, 2);
        rs1 += __shfl_xor_sync(0xffffffffu, rs1, 1);
        rs1 += __shfl_xor_sync(0xffffffffu, rs1, 2);
        ls0 += rs0; ls1 += rs1;

        // ---- O += P V (P from registers via C->A frag identity) ----
        #pragma unroll
        for (int j = 0; j < 4; j++) {
            float p00 = s[2*j][0],   p01 = s[2*j][1];
            float p02 = s[2*j][2],   p03 = s[2*j][3];
            float p10 = s[2*j+1][0], p11 = s[2*j+1][1];
            float p12 = s[2*j+1][2], p13 = s[2*j+1][3];
            float h00 = bhi(p00), h01 = bhi(p01), h02 = bhi(p02), h03 = bhi(p03);
            float h10 = bhi(p10), h11 = bhi(p11), h12 = bhi(p12), h13 = bhi(p13);
            uint32_t aph[4], apl[4];
            aph[0] = pack2(h00, h01);             apl[0] = pack2(p00-h00, p01-h01);
            aph[1] = pack2(h02, h03);             apl[1] = pack2(p02-h02, p03-h03);
            aph[2] = pack2(h10, h11);             apl[2] = pack2(p10-h10, p11-h11);
            aph[3] = pack2(h12, h13);             apl[3] = pack2(p12-h12, p13-h13);
            #pragma unroll
            for (int nb = 0; nb < 4; nb++) {
                uint32_t vh4[4], vl4[4];
                uint32_t va = vb + nb * (16 * FROWB) + j * 32;
                ldsm4(vh4, va);
                ldsm4(vl4, va + (FVL - FVH));
                mma16816(o[2 * nb],     aph, vh4[0], vh4[1]);
                mma16816(o[2 * nb],     aph, vl4[0], vl4[1]);
                mma16816(o[2 * nb],     apl, vh4[0], vh4[1]);
                mma16816(o[2 * nb + 1], aph, vh4[2], vh4[3]);
                mma16816(o[2 * nb + 1], aph, vl4[2], vl4[3]);
                mma16816(o[2 * nb + 1], apl, vh4[2], vh4[3]);
            }
        }
    }

    // ---- finalize: O /= l, write g_att ----
    int b = bh >> 4;
    int h = bh & 15;
    float i0 = 1.f / ls0, i1 = 1.f / ls1;
    int g = lane >> 2, cb = (lane & 3) * 2;
    int row0 = q0 + wid * 16 + g;
    #pragma unroll
    for (int nf = 0; nf < 8; nf++) {
        int col = h * HDD + nf * 8 + cb;
        *(float2*)&g_att[(size_t)(b * LL + row0) * HH + col] =
            make_float2(o[nf][0] * i0, o[nf][1] * i0);
        *(float2*)&g_att[(size_t)(b * LL + row0 + 8) * HH + col] =
            make_float2(o[nf][2] * i1, o[nf][3] * i1);
    }
}

// ---------------- launch ------------------------------------------------------
extern "C" void kernel_launch(void* const* d_in, const int* in_sizes, int n_in,
                              void* d_out, int out_size)
{
    const float* x     = (const float*)d_in[0];
    const float* amask = (const float*)d_in[1];
    const int*   err   = (const int*)  d_in[2];
    const float* Wq    = (const float*)d_in[3];
    const float* bq    = (const float*)d_in[4];
    const float* Wk    = (const float*)d_in[5];
    const float* bk    = (const float*)d_in[6];
    const float* Wv    = (const float*)d_in[7];
    const float* bv    = (const float*)d_in[8];
    const float* Wo    = (const float*)d_in[9];
    const float* bo    = (const float*)d_in[10];
    const float* dbias = (const float*)d_in[11];
    const float* Wg    = (const float*)d_in[12];
    const float* bg    = (const float*)d_in[13];
    float* out = (float*)d_out;

    cudaFuncSetAttribute(tgemm_kernel<0>, cudaFuncAttributeMaxDynamicSharedMemorySize, TG_SMEM);
    cudaFuncSetAttribute(tgemm_kernel<1>, cudaFuncAttributeMaxDynamicSharedMemorySize, TG_SMEM);
    cudaFuncSetAttribute(tgemm_kernel<2>, cudaFuncAttributeMaxDynamicSharedMemorySize, TG_SMEM);
    cudaFuncSetAttribute(tgemm_kernel<3>, cudaFuncAttributeMaxDynamicSharedMemorySize, TG_SMEM);
    cudaFuncSetAttribute(flash_kernel, cudaFuncAttributeMaxDynamicSharedMemorySize, FL_SMEM);

    dim3 tb(32, 8);
    dim3 tg(HH / 32, HH / 32, 4);
    wtrans_kernel<<<tg, tb>>>(Wq, Wk, Wv, Wo);

    gate_bias_kernel<<<MM, 128>>>(x, amask, err, Wg, bg, dbias);

    dim3 grid(HH / TGN, MM / TGM);   // (8, 32) = 256 CTAs
    tgemm_kernel<0><<<grid, 256, TG_SMEM>>>(x, bq, nullptr, 0);
    tgemm_kernel<1><<<grid, 256, TG_SMEM>>>(x, bk, nullptr, 1);
    tgemm_kernel<2><<<grid, 256, TG_SMEM>>>(x, bv, nullptr, 2);

    dim3 fgrid(LL / 64, BH);         // (32, 32) = 1024 CTAs
    flash_kernel<<<fgrid, 128, FL_SMEM>>>();

    tgemm_kernel<3><<<grid, 256, TG_SMEM>>>(nullptr, bo, out, 3);
}